// round 15
// baseline (speedup 1.0000x reference)
#include <cuda_runtime.h>
#include <cstdint>

#define PI_F 3.14159265358979323846f
static __device__ __align__(16) float2 g_A[33554432];  // stenciled fwd spectrum, cols m<=129
static __device__ __align__(16) float2 g_B[33554432];  // inverse pipeline
static __device__ __align__(16) float2 g_E[131072];    // [b][z][m]: y-stencil full value @ jy=128

__device__ __forceinline__ float2 cmul(float2 a, float2 b){
    return make_float2(a.x*b.x - a.y*b.y, a.x*b.y + a.y*b.x);
}
__device__ __forceinline__ float fsqrt_approx(float x){
    float r; asm("sqrt.approx.f32 %0, %1;" : "=f"(r) : "f"(x)); return r;
}
// 3-digit base-4 reversal (quads); involution.
__device__ __forceinline__ int dr3(int q){
    return ((q & 3) << 4) | (((q >> 2) & 3) << 2) | ((q >> 4) & 3);
}
// skewed shared index: breaks 64-stride bank alignment
__device__ __forceinline__ int sidx(int p){ return p + (p >> 6); }

// Pure radix-4 butterfly (twiddles pre-applied by caller).
template<int SIGN>
__device__ __forceinline__ void bfly4(float2 a0, float2 a1, float2 a2, float2 a3,
        float2& o0, float2& o1, float2& o2, float2& o3){
    float2 t02p = make_float2(a0.x+a2.x, a0.y+a2.y);
    float2 t02m = make_float2(a0.x-a2.x, a0.y-a2.y);
    float2 t13p = make_float2(a1.x+a3.x, a1.y+a3.y);
    float2 t13m = make_float2(a1.x-a3.x, a1.y-a3.y);
    float2 jt = (SIGN<0) ? make_float2(t13m.y,-t13m.x) : make_float2(-t13m.y,t13m.x);
    o0 = make_float2(t02p.x+t13p.x, t02p.y+t13p.y);
    o1 = make_float2(t02m.x+jt.x,   t02m.y+jt.y);
    o2 = make_float2(t02p.x-t13p.x, t02p.y-t13p.y);
    o3 = make_float2(t02m.x-jt.x,   t02m.y-jt.y);
}

// Radix-4 stage 0 from registers -> shared quad q, skew-indexed (shared-FFT path).
template<int SIGN>
__device__ __forceinline__ void stage0_reg(float2 a0, float2 a1, float2 a2, float2 a3,
                                           float2* s, int q){
    float2 o0,o1,o2,o3;
    bfly4<SIGN>(a0,a1,a2,a3,o0,o1,o2,o3);
    int b4 = 4*q;
    s[sidx(b4)]   = o0;
    s[sidx(b4+1)] = o1;
    s[sidx(b4+2)] = o2;
    s[sidx(b4+3)] = o3;
}

// One radix-4 butterfly of stage st (>=1) at logical index j, skew-indexed shared.
template<int SIGN>
__device__ __forceinline__ void bfly_r4(float2* s, int j, int st){
    int L = 1 << (2*st);
    int p = j & (L - 1);
    int base = ((j >> (2*st)) << (2*st + 2)) + p;
    float ang = (float)SIGN * (2.0f*PI_F) * (float)p / (float)(4*L);
    float sn, cs; __sincosf(ang, &sn, &cs);
    float2 w1 = make_float2(cs, sn);
    float2 w2 = make_float2(cs*cs - sn*sn, 2.0f*cs*sn);
    float2 w3 = cmul(w1, w2);
    int i0 = sidx(base), i1 = sidx(base+L), i2 = sidx(base+2*L), i3 = sidx(base+3*L);
    float2 o0,o1,o2,o3;
    bfly4<SIGN>(s[i0], cmul(w1,s[i1]), cmul(w2,s[i2]), cmul(w3,s[i3]), o0,o1,o2,o3);
    s[i0] = o0; s[i1] = o1; s[i2] = o2; s[i3] = o3;
}

// Stages [1, NSTAGES) on one shared line, NT threads.
template<int SIGN, int NT, int NSTAGES>
__device__ __forceinline__ void fft_mid(float2* s, int t){
#pragma unroll
    for (int st = 1; st < NSTAGES; ++st){
        __syncthreads();
#pragma unroll
        for (int k = 0; k < 64/NT; ++k) bfly_r4<SIGN>(s, t + k*NT, st);
    }
    __syncthreads();
}

// Stages [1, NSTAGES) on a pair of shared lines, 32 threads per line-pair.
template<int SIGN, int NSTAGES>
__device__ __forceinline__ void fft_mid_x2(float2* sa, float2* sb, int u){
#pragma unroll
    for (int st = 1; st < NSTAGES; ++st){
        __syncthreads();
#pragma unroll
        for (int k = 0; k < 2; ++k){
            int j = u + (k << 5);
            bfly_r4<SIGN>(sa, j, st);
            bfly_r4<SIGN>(sb, j, st);
        }
    }
    __syncthreads();
}

// Last stage (L=64) in registers from (skewed) shared. Butterfly j in [0,64).
template<int SIGN>
__device__ __forceinline__ void fft256_last(const float2* s, int j,
        float2& o0, float2& o1, float2& o2, float2& o3){
    float ang = (float)SIGN * (2.0f*PI_F) * (float)j * (1.0f/256.0f);
    float sn, cs; __sincosf(ang, &sn, &cs);
    float2 w1 = make_float2(cs, sn);
    float2 w2 = make_float2(cs*cs - sn*sn, 2.0f*cs*sn);
    float2 w3 = cmul(w1, w2);
    bfly4<SIGN>(s[sidx(j)], cmul(w1,s[sidx(j+64)]), cmul(w2,s[sidx(j+128)]),
                cmul(w3,s[sidx(j+192)]), o0,o1,o2,o3);
}

// Forward X + prep + X-STENCIL epilogue. Block: 4 lines x 64 threads.
__global__ void __launch_bounds__(256, 6) k_fwd_x(const float* __restrict__ in){
    __shared__ float2 s[4*260];
    int tid = threadIdx.x;
    int l = tid >> 6, t = tid & 63;
    int y = (blockIdx.x << 2) + l;
    int zz = blockIdx.y, bb = blockIdx.z;
    float g = (float)zz * (1.0f/127.0f);
    float g2 = g*g;
    const float* row = in + (((size_t)bb*128 + zz)*128 + y)*128;
    float2* sl = s + l*260;
    {
        float v0 = sqrtf(fmaxf(row[t]*g2, 0.0f));
        float v1 = sqrtf(fmaxf(row[t + 64]*g2, 0.0f));
        float2 z2 = make_float2(0.f, 0.f);
        stage0_reg<-1>(make_float2(v0, 0.f), make_float2(v1, 0.f), z2, z2, sl, dr3(t));
    }
    fft_mid<-1,64,4>(sl, t);
    float2* outl = g_A + (((size_t)bb*256 + zz)*256 + y)*256;
#pragma unroll
    for (int h = 0; h < 2; ++h){
        int m = t + (h << 6);
        float2 a = sl[sidx((m - 1) & 255)];
        float2 c = sl[sidx(m)];
        outl[m] = make_float2(0.5f*(a.x + c.x), 0.5f*(a.y + c.y));
    }
    if (t == 0){
        float2 c = sl[sidx(128)];
        outl[128] = make_float2(0.5f*c.x, 0.5f*c.y);
    } else if (t == 1){
        float2 a = sl[sidx(127)], c = sl[sidx(128)];
        outl[129] = make_float2(0.5f*(a.x + c.x), 0.5f*(a.y + c.y));
    }
}

// Forward Y + Y-STENCIL epilogue. Column-pair layout: 8 pairs x 32 threads.
__global__ void __launch_bounds__(256, 6) k_fwd_y(){
    __shared__ float2 s[16*261];
    int x0 = blockIdx.x << 4, zz = blockIdx.y, bb = blockIdx.z;
    int tid = threadIdx.x, xp = tid & 7, u = tid >> 3;
    bool valid = (x0 + 2*xp) <= 128;
    float2* base = g_A + ((size_t)bb << 24) + ((size_t)zz << 16) + x0;
    float4* base4 = (float4*)base;
    float2* sl0 = s + (2*xp)*261;
    float2* sl1 = sl0 + 261;
#pragma unroll
    for (int c = 0; c < 2; ++c){
        int q = (c << 5) + u;
        int n0 = dr3(q);
        float4 v0 = make_float4(0.f,0.f,0.f,0.f), v1 = v0;
        if (valid){
            v0 = base4[(size_t)n0*128 + xp];
            v1 = base4[(size_t)(n0 + 64)*128 + xp];
        }
        float2 z2 = make_float2(0.f, 0.f);
        stage0_reg<-1>(make_float2(v0.x,v0.y), make_float2(v1.x,v1.y), z2, z2, sl0, q);
        stage0_reg<-1>(make_float2(v0.z,v0.w), make_float2(v1.z,v1.w), z2, z2, sl1, q);
    }
    fft_mid_x2<-1,4>(sl0, sl1, u);
    if (valid){
#pragma unroll
        for (int c = 0; c < 8; ++c){
            int jy = (c << 5) + u;
            float2 v0, v1;
            if (jy == 128){
                float2 c0 = sl0[sidx(128)], c1 = sl1[sidx(128)];
                v0 = make_float2(0.5f*c0.x, 0.5f*c0.y);
                v1 = make_float2(0.5f*c1.x, 0.5f*c1.y);
            } else {
                int jm = (jy - 1) & 255;
                float2 a0 = sl0[sidx(jm)], c0 = sl0[sidx(jy)];
                float2 a1 = sl1[sidx(jm)], c1 = sl1[sidx(jy)];
                v0 = make_float2(0.5f*(a0.x + c0.x), 0.5f*(a0.y + c0.y));
                v1 = make_float2(0.5f*(a1.x + c1.x), 0.5f*(a1.y + c1.y));
            }
            base4[(size_t)jy*128 + xp] = make_float4(v0.x, v0.y, v1.x, v1.y);
        }
        if (u == 0){
            float2 a0 = sl0[sidx(127)], c0 = sl0[sidx(128)];
            float2 a1 = sl1[sidx(127)], c1 = sl1[sidx(128)];
            float4* E4 = (float4*)(g_E + ((size_t)bb << 16) + ((size_t)zz << 8) + x0);
            E4[xp] = make_float4(0.5f*(a0.x + c0.x), 0.5f*(a0.y + c0.y),
                                 0.5f*(a1.x + c1.x), 0.5f*(a1.y + c1.y));
        }
    }
}

// Forward Z (merged: blockIdx.y==256 handles the g_E side buffer).
__global__ void __launch_bounds__(256, 6) k_fwd_z(){
    __shared__ float2 s[16*261];
    int x0 = blockIdx.x << 4, y = blockIdx.y, bb = blockIdx.z;
    int tid = threadIdx.x, xp = tid & 7, u = tid >> 3;
    bool valid = (x0 + 2*xp) <= 128;
    bool isE = (y == 256);
    float2* base = isE ? (g_E + ((size_t)bb << 16) + x0)
                       : (g_A + ((size_t)bb << 24) + ((size_t)y << 8) + x0);
    size_t zs4 = isE ? 128 : 32768;
    float4* base4 = (float4*)base;
    float2* sl0 = s + (2*xp)*261;
    float2* sl1 = sl0 + 261;
#pragma unroll
    for (int c = 0; c < 2; ++c){
        int q = (c << 5) + u;
        int n0 = dr3(q);
        float4 v0 = make_float4(0.f,0.f,0.f,0.f), v1 = v0;
        if (valid){
            v0 = base4[(size_t)n0*zs4 + xp];
            v1 = base4[(size_t)(n0 + 64)*zs4 + xp];
        }
        float2 z2 = make_float2(0.f, 0.f);
        stage0_reg<-1>(make_float2(v0.x,v0.y), make_float2(v1.x,v1.y), z2, z2, sl0, q);
        stage0_reg<-1>(make_float2(v0.z,v0.w), make_float2(v1.z,v1.w), z2, z2, sl1, q);
    }
    fft_mid_x2<-1,3>(sl0, sl1, u);
    if (valid){
#pragma unroll
        for (int k = 0; k < 2; ++k){
            int j = (k << 5) + u;
            float2 a0,a1,a2,a3, c0,c1,c2,c3;
            fft256_last<-1>(sl0, j, a0,a1,a2,a3);
            fft256_last<-1>(sl1, j, c0,c1,c2,c3);
            base4[(size_t)j*zs4 + xp]         = make_float4(a0.x,a0.y,c0.x,c0.y);
            base4[(size_t)(j + 64)*zs4 + xp]  = make_float4(a1.x,a1.y,c1.x,c1.y);
            base4[(size_t)(j + 128)*zs4 + xp] = make_float4(a2.x,a2.y,c2.x,c2.y);
            base4[(size_t)(j + 192)*zs4 + xp] = make_float4(a3.x,a3.y,c3.x,c3.y);
        }
    }
}

// Fused Stolt z-interp + inverse X FFT, REGISTER-FFT version.
// Block: 16 jy-lines x 16 threads. Thread t handles jx = t + 16k (16 samples).
// Region split is compile-time per k: k<=7 direct, k>=9 conj, k==8 mixed.
__global__ void __launch_bounds__(256, 6) k_resample_invx(){
    __shared__ float2 s[16*272];
    int tid = threadIdx.x;
    int line = tid >> 4, t = tid & 15;
    int jy = (blockIdx.x << 4) + line;
    int jz = blockIdx.y + 1;        // 1..127
    int bb = blockIdx.z;
    int sy = jy ^ 128;
    float gz = (float)jz * (1.0f/128.0f);
    float gy = (float)(sy - 128) * (1.0f/128.0f);
    const float fk = 0.1024f;
    float gyz = fk*gy*gy + gz*gz;
    const float2* Ab = g_A + ((size_t)bb << 24);
    // direct-region row base: + (zp<<16) + jx
    const float2* Ad = Ab + ((size_t)jy << 8);
    // conj-region base + z-stride (g_E for jy==129, mirrored g_A row otherwise)
    int ry = (jy == 128) ? 128 : ((257 - jy) & 255);
    bool useE = (jy == 129);
    const float2* Pc = useE ? (g_E + ((size_t)bb << 16)) : (Ab + ((size_t)ry << 8));
    const size_t zstr = useE ? 256 : 65536;

    float2 v[16];
#pragma unroll
    for (int k = 0; k < 16; ++k){
        int jx = t + (k << 4);
        int sx = jx ^ 128;
        float gx = (float)(sx - 128) * (1.0f/128.0f);
        float gznew = fsqrt_approx(fk*gx*gx + gyz);
        float pz = (gznew + 1.0f)*128.0f - 0.5f;    // >= 128.5
        float z0f = floorf(pz);
        float dz = pz - z0f;
        int z0u = (int)z0f - 128;                   // >= 0
        float accx = 0.f, accy = 0.f;
        if (k <= 7){
            // jx <= 127: always direct
#pragma unroll
            for (int tz = 0; tz < 2; ++tz){
                int zp = z0u + tz;
                if (zp > 127) continue;
                float w = tz ? dz : (1.0f - dz);
                float2 vv = __ldg(&Ad[((size_t)zp << 16) + (size_t)jx]);
                accx += w*vv.x; accy += w*vv.y;
            }
        } else if (k >= 9){
            // jx >= 144: always conj
            int m = 257 - jx;
#pragma unroll
            for (int tz = 0; tz < 2; ++tz){
                int zp = z0u + tz;
                if (zp > 127) continue;
                float w = tz ? dz : (1.0f - dz);
                int zq = (256 - zp) & 255;
                float2 e = __ldg(&Pc[(size_t)zq * zstr + (size_t)m]);
                accx += w*e.x; accy -= w*e.y;
            }
        } else {
            // k == 8: jx = t + 128 (t==0 direct, else conj)
            int m = (jx == 129) ? 129 : (257 - jx);
#pragma unroll
            for (int tz = 0; tz < 2; ++tz){
                int zp = z0u + tz;
                if (zp > 127) continue;
                float w = tz ? dz : (1.0f - dz);
                float2 vv;
                if (t == 0){
                    vv = __ldg(&Ad[((size_t)zp << 16) + 128]);
                } else {
                    int zq = (256 - zp) & 255;
                    float2 e = __ldg(&Pc[(size_t)zq * zstr + (size_t)m]);
                    vv = make_float2(e.x, -e.y);
                }
                accx += w*vv.x; accy += w*vv.y;
            }
        }
        float fac = __fdividef(gz, gznew + 1e-8f) * (1.0f/256.0f);
        v[k] = make_float2(accx*fac, accy*fac);
    }

    // ---- stage 0 in registers (no twiddle). Output L[4k0+r] at v-slot [k0+4r].
#pragma unroll
    for (int k0 = 0; k0 < 4; ++k0){
        bfly4<1>(v[k0], v[k0+4], v[k0+8], v[k0+12],
                 v[k0], v[k0+4], v[k0+8], v[k0+12]);
    }
    // ---- stage 1 in registers, compile-time twiddles.
    {
        const float TC[4] = {1.0f, 0.92387953251f, 0.70710678119f, 0.38268343236f};
        const float TS[4] = {0.0f, 0.38268343236f, 0.70710678119f, 0.92387953251f};
#pragma unroll
        for (int p = 0; p < 4; ++p){
            float2 w1 = make_float2(TC[p], TS[p]);       // SIGN=+1
            float2 w2 = cmul(w1, w1);
            float2 w3 = cmul(w1, w2);
            bfly4<1>(v[4*p], cmul(w1, v[4*p+1]), cmul(w2, v[4*p+2]), cmul(w3, v[4*p+3]),
                     v[4*p], v[4*p+1], v[4*p+2], v[4*p+3]);
        }
    }
    // ---- transpose through shared.
    {
        float2* SL = s + line*272;
        int sg = 17*(4*(t & 3) + (t >> 2));
#pragma unroll
        for (int i = 0; i < 16; ++i)
            SL[sg + i] = v[4*(i & 3) + (i >> 2)];
        __syncthreads();
#pragma unroll
        for (int m = 0; m < 16; ++m)
            v[m] = SL[17*m + t];          // position 16m + t
    }
    // ---- stages 2+3 in registers; one sincos, stage-2 twiddle derived as wb^4.
    {
        float sn, cs; __sincosf((2.0f*PI_F/256.0f)*(float)t, &sn, &cs);
        float2 wb  = make_float2(cs, sn);        // e^{2pi i t/256} (stage 3 base)
        float2 wb2 = cmul(wb, wb);
        float2 w1s = cmul(wb2, wb2);             // e^{2pi i t/64}  (stage 2)
        {
            float2 w2 = cmul(w1s, w1s);
            float2 w3 = cmul(w1s, w2);
#pragma unroll
            for (int h = 0; h < 4; ++h){
                bfly4<1>(v[4*h], cmul(w1s, v[4*h+1]), cmul(w2, v[4*h+2]), cmul(w3, v[4*h+3]),
                         v[4*h], v[4*h+1], v[4*h+2], v[4*h+3]);
            }
        }
        const float TC[4] = {1.0f, 0.92387953251f, 0.70710678119f, 0.38268343236f};
        const float TS[4] = {0.0f, 0.38268343236f, 0.70710678119f, 0.92387953251f};
        float2* outl = g_B + ((size_t)bb << 24) + ((size_t)jz << 16) + ((size_t)jy << 8);
#pragma unroll
        for (int m0 = 0; m0 < 4; ++m0){
            float2 w1 = cmul(wb, make_float2(TC[m0], TS[m0]));
            float2 w2 = cmul(w1, w1);
            float2 w3 = cmul(w1, w2);
            float2 o0,o1,o2,o3;
            bfly4<1>(v[m0], cmul(w1, v[m0+4]), cmul(w2, v[m0+8]), cmul(w3, v[m0+12]),
                     o0,o1,o2,o3);
            outl[16*m0 + t]      = o0;     // x = 16*m0 + t      (< 64)
            outl[16*m0 + 64 + t] = o1;     // x = 16*(m0+4) + t  (< 128)
        }
    }
}

// Inverse Y: full 256-y input, write y<128 scaled. Column-pair layout.
__global__ void __launch_bounds__(256, 6) k_inv_y(){
    __shared__ float2 s[16*261];
    int x0 = blockIdx.x << 4, zz = blockIdx.y + 1, bb = blockIdx.z;
    int tid = threadIdx.x, xp = tid & 7, u = tid >> 3;
    float2* base = g_B + ((size_t)bb << 24) + ((size_t)zz << 16) + x0;
    float4* base4 = (float4*)base;
    float2* sl0 = s + (2*xp)*261;
    float2* sl1 = sl0 + 261;
#pragma unroll
    for (int c = 0; c < 2; ++c){
        int q = (c << 5) + u;
        int n0 = dr3(q);
        float4 v0 = base4[(size_t)n0*128 + xp];
        float4 v1 = base4[(size_t)(n0 + 64)*128 + xp];
        float4 v2 = base4[(size_t)(n0 + 128)*128 + xp];
        float4 v3 = base4[(size_t)(n0 + 192)*128 + xp];
        stage0_reg<1>(make_float2(v0.x,v0.y), make_float2(v1.x,v1.y),
                      make_float2(v2.x,v2.y), make_float2(v3.x,v3.y), sl0, q);
        stage0_reg<1>(make_float2(v0.z,v0.w), make_float2(v1.z,v1.w),
                      make_float2(v2.z,v2.w), make_float2(v3.z,v3.w), sl1, q);
    }
    fft_mid_x2<1,3>(sl0, sl1, u);
#pragma unroll
    for (int k = 0; k < 2; ++k){
        int j = (k << 5) + u;               // < 64
        float2 a0,a1,a2,a3, c0,c1,c2,c3;
        fft256_last<1>(sl0, j, a0,a1,a2,a3);
        fft256_last<1>(sl1, j, c0,c1,c2,c3);
        const float sc = 1.f/256.f;
        base4[(size_t)j*128 + xp]        = make_float4(a0.x*sc, a0.y*sc, c0.x*sc, c0.y*sc);
        base4[(size_t)(j + 64)*128 + xp] = make_float4(a1.x*sc, a1.y*sc, c1.x*sc, c1.y*sc);
    }
}

// Inverse Z: z in [1,128) nonzero, upper half zero-padded. Writes Re to output.
__global__ void __launch_bounds__(256, 6) k_inv_z(float* __restrict__ out){
    __shared__ float2 s[16*261];
    int x0 = blockIdx.x << 4, y = blockIdx.y, bb = blockIdx.z;
    int tid = threadIdx.x, xp = tid & 7, u = tid >> 3;
    const float2* base = g_B + ((size_t)bb << 24) + ((size_t)y << 8) + x0;
    const float4* base4 = (const float4*)base;
    float2* sl0 = s + (2*xp)*261;
    float2* sl1 = sl0 + 261;
#pragma unroll
    for (int c = 0; c < 2; ++c){
        int q = (c << 5) + u;
        int n0 = dr3(q);
        float4 v0 = make_float4(0.f,0.f,0.f,0.f);
        if (n0 >= 1) v0 = base4[(size_t)n0*32768 + xp];
        float4 v1 = base4[(size_t)(n0 + 64)*32768 + xp];
        float2 z2 = make_float2(0.f, 0.f);
        stage0_reg<1>(make_float2(v0.x,v0.y), make_float2(v1.x,v1.y), z2, z2, sl0, q);
        stage0_reg<1>(make_float2(v0.z,v0.w), make_float2(v1.z,v1.w), z2, z2, sl1, q);
    }
    fft_mid_x2<1,3>(sl0, sl1, u);
    float* ob = out + ((size_t)bb << 21) + (size_t)y*128 + (size_t)(x0 + 2*xp);
#pragma unroll
    for (int k = 0; k < 2; ++k){
        int j = (k << 5) + u;               // < 64
        float2 a0,a1,a2,a3, c0,c1,c2,c3;
        fft256_last<1>(sl0, j, a0,a1,a2,a3);
        fft256_last<1>(sl1, j, c0,c1,c2,c3);
        const float sc = 1.f/256.f;
        *(float2*)(ob + (size_t)j*16384)        = make_float2(a0.x*sc, c0.x*sc);
        *(float2*)(ob + (size_t)(j + 64)*16384) = make_float2(a1.x*sc, c1.x*sc);
    }
}

extern "C" void kernel_launch(void* const* d_in, const int* in_sizes, int n_in,
                              void* d_out, int out_size){
    (void)in_sizes; (void)n_in; (void)out_size;
    const float* in = (const float*)d_in[0];
    float* out = (float*)d_out;

    k_fwd_x        <<<dim3(32, 128, 2), 256>>>(in);
    k_fwd_y        <<<dim3(9,  128, 2), 256>>>();
    k_fwd_z        <<<dim3(9,  257, 2), 256>>>();
    k_resample_invx<<<dim3(16, 127, 2), 256>>>();
    k_inv_y        <<<dim3(8,  127, 2), 256>>>();
    k_inv_z        <<<dim3(8,  128, 2), 256>>>(out);
}

// round 16
// speedup vs baseline: 1.1087x; 1.1087x over previous
#include <cuda_runtime.h>
#include <cstdint>

#define PI_F 3.14159265358979323846f
static __device__ __align__(16) float2 g_A[33554432];  // stenciled fwd spectrum, cols m<=129
static __device__ __align__(16) float2 g_B[33554432];  // inverse pipeline
static __device__ __align__(16) float2 g_E[131072];    // [b][z][m]: y-stencil full value @ jy=128

__device__ __forceinline__ float2 cmul(float2 a, float2 b){
    return make_float2(a.x*b.x - a.y*b.y, a.x*b.y + a.y*b.x);
}
__device__ __forceinline__ float fsqrt_approx(float x){
    float r; asm("sqrt.approx.f32 %0, %1;" : "=f"(r) : "f"(x)); return r;
}
// 3-digit base-4 reversal (quads); involution.
__device__ __forceinline__ int dr3(int q){
    return ((q & 3) << 4) | (((q >> 2) & 3) << 2) | ((q >> 4) & 3);
}
// skewed shared index: breaks 64-stride bank alignment
__device__ __forceinline__ int sidx(int p){ return p + (p >> 6); }

// Pure radix-4 butterfly (twiddles pre-applied by caller).
template<int SIGN>
__device__ __forceinline__ void bfly4(float2 a0, float2 a1, float2 a2, float2 a3,
        float2& o0, float2& o1, float2& o2, float2& o3){
    float2 t02p = make_float2(a0.x+a2.x, a0.y+a2.y);
    float2 t02m = make_float2(a0.x-a2.x, a0.y-a2.y);
    float2 t13p = make_float2(a1.x+a3.x, a1.y+a3.y);
    float2 t13m = make_float2(a1.x-a3.x, a1.y-a3.y);
    float2 jt = (SIGN<0) ? make_float2(t13m.y,-t13m.x) : make_float2(-t13m.y,t13m.x);
    o0 = make_float2(t02p.x+t13p.x, t02p.y+t13p.y);
    o1 = make_float2(t02m.x+jt.x,   t02m.y+jt.y);
    o2 = make_float2(t02p.x-t13p.x, t02p.y-t13p.y);
    o3 = make_float2(t02m.x-jt.x,   t02m.y-jt.y);
}

// Radix-4 stage 0 from registers -> shared quad q, skew-indexed (shared-FFT path).
template<int SIGN>
__device__ __forceinline__ void stage0_reg(float2 a0, float2 a1, float2 a2, float2 a3,
                                           float2* s, int q){
    float2 o0,o1,o2,o3;
    bfly4<SIGN>(a0,a1,a2,a3,o0,o1,o2,o3);
    int b4 = 4*q;
    s[sidx(b4)]   = o0;
    s[sidx(b4+1)] = o1;
    s[sidx(b4+2)] = o2;
    s[sidx(b4+3)] = o3;
}

// One radix-4 butterfly of stage st (>=1) at logical index j, skew-indexed shared.
template<int SIGN>
__device__ __forceinline__ void bfly_r4(float2* s, int j, int st){
    int L = 1 << (2*st);
    int p = j & (L - 1);
    int base = ((j >> (2*st)) << (2*st + 2)) + p;
    float ang = (float)SIGN * (2.0f*PI_F) * (float)p / (float)(4*L);
    float sn, cs; __sincosf(ang, &sn, &cs);
    float2 w1 = make_float2(cs, sn);
    float2 w2 = make_float2(cs*cs - sn*sn, 2.0f*cs*sn);
    float2 w3 = cmul(w1, w2);
    int i0 = sidx(base), i1 = sidx(base+L), i2 = sidx(base+2*L), i3 = sidx(base+3*L);
    float2 o0,o1,o2,o3;
    bfly4<SIGN>(s[i0], cmul(w1,s[i1]), cmul(w2,s[i2]), cmul(w3,s[i3]), o0,o1,o2,o3);
    s[i0] = o0; s[i1] = o1; s[i2] = o2; s[i3] = o3;
}

// Stages [1, NSTAGES) on one shared line, NT threads.
template<int SIGN, int NT, int NSTAGES>
__device__ __forceinline__ void fft_mid(float2* s, int t){
#pragma unroll
    for (int st = 1; st < NSTAGES; ++st){
        __syncthreads();
#pragma unroll
        for (int k = 0; k < 64/NT; ++k) bfly_r4<SIGN>(s, t + k*NT, st);
    }
    __syncthreads();
}

// Stages [1, NSTAGES) on a pair of shared lines, 32 threads per line-pair.
template<int SIGN, int NSTAGES>
__device__ __forceinline__ void fft_mid_x2(float2* sa, float2* sb, int u){
#pragma unroll
    for (int st = 1; st < NSTAGES; ++st){
        __syncthreads();
#pragma unroll
        for (int k = 0; k < 2; ++k){
            int j = u + (k << 5);
            bfly_r4<SIGN>(sa, j, st);
            bfly_r4<SIGN>(sb, j, st);
        }
    }
    __syncthreads();
}

// Last stage (L=64) in registers from (skewed) shared. Butterfly j in [0,64).
template<int SIGN>
__device__ __forceinline__ void fft256_last(const float2* s, int j,
        float2& o0, float2& o1, float2& o2, float2& o3){
    float ang = (float)SIGN * (2.0f*PI_F) * (float)j * (1.0f/256.0f);
    float sn, cs; __sincosf(ang, &sn, &cs);
    float2 w1 = make_float2(cs, sn);
    float2 w2 = make_float2(cs*cs - sn*sn, 2.0f*cs*sn);
    float2 w3 = cmul(w1, w2);
    bfly4<SIGN>(s[sidx(j)], cmul(w1,s[sidx(j+64)]), cmul(w2,s[sidx(j+128)]),
                cmul(w3,s[sidx(j+192)]), o0,o1,o2,o3);
}

// Forward X + prep + X-STENCIL epilogue. Block: 4 lines x 64 threads.
__global__ void __launch_bounds__(256, 6) k_fwd_x(const float* __restrict__ in){
    __shared__ float2 s[4*260];
    int tid = threadIdx.x;
    int l = tid >> 6, t = tid & 63;
    int y = (blockIdx.x << 2) + l;
    int zz = blockIdx.y, bb = blockIdx.z;
    float g = (float)zz * (1.0f/127.0f);
    float g2 = g*g;
    const float* row = in + (((size_t)bb*128 + zz)*128 + y)*128;
    float2* sl = s + l*260;
    {
        float v0 = sqrtf(fmaxf(row[t]*g2, 0.0f));
        float v1 = sqrtf(fmaxf(row[t + 64]*g2, 0.0f));
        float2 z2 = make_float2(0.f, 0.f);
        stage0_reg<-1>(make_float2(v0, 0.f), make_float2(v1, 0.f), z2, z2, sl, dr3(t));
    }
    fft_mid<-1,64,4>(sl, t);
    float2* outl = g_A + (((size_t)bb*256 + zz)*256 + y)*256;
#pragma unroll
    for (int h = 0; h < 2; ++h){
        int m = t + (h << 6);
        float2 a = sl[sidx((m - 1) & 255)];
        float2 c = sl[sidx(m)];
        outl[m] = make_float2(0.5f*(a.x + c.x), 0.5f*(a.y + c.y));
    }
    if (t == 0){
        float2 c = sl[sidx(128)];
        outl[128] = make_float2(0.5f*c.x, 0.5f*c.y);
    } else if (t == 1){
        float2 a = sl[sidx(127)], c = sl[sidx(128)];
        outl[129] = make_float2(0.5f*(a.x + c.x), 0.5f*(a.y + c.y));
    }
}

// Forward Y + Y-STENCIL epilogue. Column-pair layout: 8 pairs x 32 threads.
__global__ void __launch_bounds__(256, 6) k_fwd_y(){
    __shared__ float2 s[16*261];
    int x0 = blockIdx.x << 4, zz = blockIdx.y, bb = blockIdx.z;
    int tid = threadIdx.x, xp = tid & 7, u = tid >> 3;
    bool valid = (x0 + 2*xp) <= 128;
    float2* base = g_A + ((size_t)bb << 24) + ((size_t)zz << 16) + x0;
    float4* base4 = (float4*)base;
    float2* sl0 = s + (2*xp)*261;
    float2* sl1 = sl0 + 261;
#pragma unroll
    for (int c = 0; c < 2; ++c){
        int q = (c << 5) + u;
        int n0 = dr3(q);
        float4 v0 = make_float4(0.f,0.f,0.f,0.f), v1 = v0;
        if (valid){
            v0 = base4[(size_t)n0*128 + xp];
            v1 = base4[(size_t)(n0 + 64)*128 + xp];
        }
        float2 z2 = make_float2(0.f, 0.f);
        stage0_reg<-1>(make_float2(v0.x,v0.y), make_float2(v1.x,v1.y), z2, z2, sl0, q);
        stage0_reg<-1>(make_float2(v0.z,v0.w), make_float2(v1.z,v1.w), z2, z2, sl1, q);
    }
    fft_mid_x2<-1,4>(sl0, sl1, u);
    if (valid){
#pragma unroll
        for (int c = 0; c < 8; ++c){
            int jy = (c << 5) + u;
            float2 v0, v1;
            if (jy == 128){
                float2 c0 = sl0[sidx(128)], c1 = sl1[sidx(128)];
                v0 = make_float2(0.5f*c0.x, 0.5f*c0.y);
                v1 = make_float2(0.5f*c1.x, 0.5f*c1.y);
            } else {
                int jm = (jy - 1) & 255;
                float2 a0 = sl0[sidx(jm)], c0 = sl0[sidx(jy)];
                float2 a1 = sl1[sidx(jm)], c1 = sl1[sidx(jy)];
                v0 = make_float2(0.5f*(a0.x + c0.x), 0.5f*(a0.y + c0.y));
                v1 = make_float2(0.5f*(a1.x + c1.x), 0.5f*(a1.y + c1.y));
            }
            base4[(size_t)jy*128 + xp] = make_float4(v0.x, v0.y, v1.x, v1.y);
        }
        if (u == 0){
            float2 a0 = sl0[sidx(127)], c0 = sl0[sidx(128)];
            float2 a1 = sl1[sidx(127)], c1 = sl1[sidx(128)];
            float4* E4 = (float4*)(g_E + ((size_t)bb << 16) + ((size_t)zz << 8) + x0);
            E4[xp] = make_float4(0.5f*(a0.x + c0.x), 0.5f*(a0.y + c0.y),
                                 0.5f*(a1.x + c1.x), 0.5f*(a1.y + c1.y));
        }
    }
}

// Forward Z (merged: blockIdx.y==256 handles the g_E side buffer).
__global__ void __launch_bounds__(256, 6) k_fwd_z(){
    __shared__ float2 s[16*261];
    int x0 = blockIdx.x << 4, y = blockIdx.y, bb = blockIdx.z;
    int tid = threadIdx.x, xp = tid & 7, u = tid >> 3;
    bool valid = (x0 + 2*xp) <= 128;
    bool isE = (y == 256);
    float2* base = isE ? (g_E + ((size_t)bb << 16) + x0)
                       : (g_A + ((size_t)bb << 24) + ((size_t)y << 8) + x0);
    size_t zs4 = isE ? 128 : 32768;
    float4* base4 = (float4*)base;
    float2* sl0 = s + (2*xp)*261;
    float2* sl1 = sl0 + 261;
#pragma unroll
    for (int c = 0; c < 2; ++c){
        int q = (c << 5) + u;
        int n0 = dr3(q);
        float4 v0 = make_float4(0.f,0.f,0.f,0.f), v1 = v0;
        if (valid){
            v0 = base4[(size_t)n0*zs4 + xp];
            v1 = base4[(size_t)(n0 + 64)*zs4 + xp];
        }
        float2 z2 = make_float2(0.f, 0.f);
        stage0_reg<-1>(make_float2(v0.x,v0.y), make_float2(v1.x,v1.y), z2, z2, sl0, q);
        stage0_reg<-1>(make_float2(v0.z,v0.w), make_float2(v1.z,v1.w), z2, z2, sl1, q);
    }
    fft_mid_x2<-1,3>(sl0, sl1, u);
    if (valid){
#pragma unroll
        for (int k = 0; k < 2; ++k){
            int j = (k << 5) + u;
            float2 a0,a1,a2,a3, c0,c1,c2,c3;
            fft256_last<-1>(sl0, j, a0,a1,a2,a3);
            fft256_last<-1>(sl1, j, c0,c1,c2,c3);
            base4[(size_t)j*zs4 + xp]         = make_float4(a0.x,a0.y,c0.x,c0.y);
            base4[(size_t)(j + 64)*zs4 + xp]  = make_float4(a1.x,a1.y,c1.x,c1.y);
            base4[(size_t)(j + 128)*zs4 + xp] = make_float4(a2.x,a2.y,c2.x,c2.y);
            base4[(size_t)(j + 192)*zs4 + xp] = make_float4(a3.x,a3.y,c3.x,c3.y);
        }
    }
}

// Fused Stolt z-interp + inverse X FFT, REGISTER-FFT version.
// Block: 16 jy-lines x 16 threads. Thread t handles jx = t + 16k (16 samples).
// Region split compile-time per k (k<=7 direct, k>=9 conj, k==8 mixed).
// Occupancy 5 (NOT 6): the gather needs ~48 regs to keep 32 loads in flight.
__global__ void __launch_bounds__(256, 5) k_resample_invx(){
    __shared__ float2 s[16*272];
    int tid = threadIdx.x;
    int line = tid >> 4, t = tid & 15;
    int jy = (blockIdx.x << 4) + line;
    int jz = blockIdx.y + 1;        // 1..127
    int bb = blockIdx.z;
    int sy = jy ^ 128;
    float gz = (float)jz * (1.0f/128.0f);
    float gy = (float)(sy - 128) * (1.0f/128.0f);
    const float fk = 0.1024f;
    float gyz = fk*gy*gy + gz*gz;
    const float2* Ab = g_A + ((size_t)bb << 24);
    const float2* Ad = Ab + ((size_t)jy << 8);      // direct row base
    int ry = (jy == 128) ? 128 : ((257 - jy) & 255);
    bool useE = (jy == 129);
    const float2* Pc = useE ? (g_E + ((size_t)bb << 16)) : (Ab + ((size_t)ry << 8));
    const size_t zstr = useE ? 256 : 65536;

    float2 v[16];
#pragma unroll
    for (int k = 0; k < 16; ++k){
        int jx = t + (k << 4);
        int sx = jx ^ 128;
        float gx = (float)(sx - 128) * (1.0f/128.0f);
        float gznew = fsqrt_approx(fk*gx*gx + gyz);
        float pz = (gznew + 1.0f)*128.0f - 0.5f;    // >= 128.5
        float z0f = floorf(pz);
        float dz = pz - z0f;
        int z0u = (int)z0f - 128;                   // >= 0
        float accx = 0.f, accy = 0.f;
        if (k <= 7){
            // jx <= 127: always direct
#pragma unroll
            for (int tz = 0; tz < 2; ++tz){
                int zp = z0u + tz;
                if (zp > 127) continue;
                float w = tz ? dz : (1.0f - dz);
                float2 vv = __ldg(&Ad[((size_t)zp << 16) + (size_t)jx]);
                accx += w*vv.x; accy += w*vv.y;
            }
        } else if (k >= 9){
            // jx >= 144: always conj
            int m = 257 - jx;
#pragma unroll
            for (int tz = 0; tz < 2; ++tz){
                int zp = z0u + tz;
                if (zp > 127) continue;
                float w = tz ? dz : (1.0f - dz);
                int zq = (256 - zp) & 255;
                float2 e = __ldg(&Pc[(size_t)zq * zstr + (size_t)m]);
                accx += w*e.x; accy -= w*e.y;
            }
        } else {
            // k == 8: jx = t + 128 (t==0 direct, else conj)
            int m = (jx == 129) ? 129 : (257 - jx);
#pragma unroll
            for (int tz = 0; tz < 2; ++tz){
                int zp = z0u + tz;
                if (zp > 127) continue;
                float w = tz ? dz : (1.0f - dz);
                float2 vv;
                if (t == 0){
                    vv = __ldg(&Ad[((size_t)zp << 16) + 128]);
                } else {
                    int zq = (256 - zp) & 255;
                    float2 e = __ldg(&Pc[(size_t)zq * zstr + (size_t)m]);
                    vv = make_float2(e.x, -e.y);
                }
                accx += w*vv.x; accy += w*vv.y;
            }
        }
        float fac = __fdividef(gz, gznew + 1e-8f) * (1.0f/256.0f);
        v[k] = make_float2(accx*fac, accy*fac);
    }

    // ---- stage 0 in registers (no twiddle). Output L[4k0+r] at v-slot [k0+4r].
#pragma unroll
    for (int k0 = 0; k0 < 4; ++k0){
        bfly4<1>(v[k0], v[k0+4], v[k0+8], v[k0+12],
                 v[k0], v[k0+4], v[k0+8], v[k0+12]);
    }
    // ---- stage 1 in registers, compile-time twiddles.
    {
        const float TC[4] = {1.0f, 0.92387953251f, 0.70710678119f, 0.38268343236f};
        const float TS[4] = {0.0f, 0.38268343236f, 0.70710678119f, 0.92387953251f};
#pragma unroll
        for (int p = 0; p < 4; ++p){
            float2 w1 = make_float2(TC[p], TS[p]);       // SIGN=+1
            float2 w2 = cmul(w1, w1);
            float2 w3 = cmul(w1, w2);
            bfly4<1>(v[4*p], cmul(w1, v[4*p+1]), cmul(w2, v[4*p+2]), cmul(w3, v[4*p+3]),
                     v[4*p], v[4*p+1], v[4*p+2], v[4*p+3]);
        }
    }
    // ---- transpose through shared.
    {
        float2* SL = s + line*272;
        int sg = 17*(4*(t & 3) + (t >> 2));
#pragma unroll
        for (int i = 0; i < 16; ++i)
            SL[sg + i] = v[4*(i & 3) + (i >> 2)];
        __syncthreads();
#pragma unroll
        for (int m = 0; m < 16; ++m)
            v[m] = SL[17*m + t];          // position 16m + t
    }
    // ---- stages 2+3 in registers; one sincos, stage-2 twiddle derived as wb^4.
    {
        float sn, cs; __sincosf((2.0f*PI_F/256.0f)*(float)t, &sn, &cs);
        float2 wb  = make_float2(cs, sn);        // e^{2pi i t/256} (stage 3 base)
        float2 wb2 = cmul(wb, wb);
        float2 w1s = cmul(wb2, wb2);             // e^{2pi i t/64}  (stage 2)
        {
            float2 w2 = cmul(w1s, w1s);
            float2 w3 = cmul(w1s, w2);
#pragma unroll
            for (int h = 0; h < 4; ++h){
                bfly4<1>(v[4*h], cmul(w1s, v[4*h+1]), cmul(w2, v[4*h+2]), cmul(w3, v[4*h+3]),
                         v[4*h], v[4*h+1], v[4*h+2], v[4*h+3]);
            }
        }
        const float TC[4] = {1.0f, 0.92387953251f, 0.70710678119f, 0.38268343236f};
        const float TS[4] = {0.0f, 0.38268343236f, 0.70710678119f, 0.92387953251f};
        float2* outl = g_B + ((size_t)bb << 24) + ((size_t)jz << 16) + ((size_t)jy << 8);
#pragma unroll
        for (int m0 = 0; m0 < 4; ++m0){
            float2 w1 = cmul(wb, make_float2(TC[m0], TS[m0]));
            float2 w2 = cmul(w1, w1);
            float2 w3 = cmul(w1, w2);
            float2 o0,o1,o2,o3;
            bfly4<1>(v[m0], cmul(w1, v[m0+4]), cmul(w2, v[m0+8]), cmul(w3, v[m0+12]),
                     o0,o1,o2,o3);
            outl[16*m0 + t]      = o0;     // x = 16*m0 + t      (< 64)
            outl[16*m0 + 64 + t] = o1;     // x = 16*(m0+4) + t  (< 128)
        }
    }
}

// Inverse Y: full 256-y input, write y<128 scaled. Column-pair layout.
__global__ void __launch_bounds__(256, 6) k_inv_y(){
    __shared__ float2 s[16*261];
    int x0 = blockIdx.x << 4, zz = blockIdx.y + 1, bb = blockIdx.z;
    int tid = threadIdx.x, xp = tid & 7, u = tid >> 3;
    float2* base = g_B + ((size_t)bb << 24) + ((size_t)zz << 16) + x0;
    float4* base4 = (float4*)base;
    float2* sl0 = s + (2*xp)*261;
    float2* sl1 = sl0 + 261;
#pragma unroll
    for (int c = 0; c < 2; ++c){
        int q = (c << 5) + u;
        int n0 = dr3(q);
        float4 v0 = base4[(size_t)n0*128 + xp];
        float4 v1 = base4[(size_t)(n0 + 64)*128 + xp];
        float4 v2 = base4[(size_t)(n0 + 128)*128 + xp];
        float4 v3 = base4[(size_t)(n0 + 192)*128 + xp];
        stage0_reg<1>(make_float2(v0.x,v0.y), make_float2(v1.x,v1.y),
                      make_float2(v2.x,v2.y), make_float2(v3.x,v3.y), sl0, q);
        stage0_reg<1>(make_float2(v0.z,v0.w), make_float2(v1.z,v1.w),
                      make_float2(v2.z,v2.w), make_float2(v3.z,v3.w), sl1, q);
    }
    fft_mid_x2<1,3>(sl0, sl1, u);
#pragma unroll
    for (int k = 0; k < 2; ++k){
        int j = (k << 5) + u;               // < 64
        float2 a0,a1,a2,a3, c0,c1,c2,c3;
        fft256_last<1>(sl0, j, a0,a1,a2,a3);
        fft256_last<1>(sl1, j, c0,c1,c2,c3);
        const float sc = 1.f/256.f;
        base4[(size_t)j*128 + xp]        = make_float4(a0.x*sc, a0.y*sc, c0.x*sc, c0.y*sc);
        base4[(size_t)(j + 64)*128 + xp] = make_float4(a1.x*sc, a1.y*sc, c1.x*sc, c1.y*sc);
    }
}

// Inverse Z: z in [1,128) nonzero, upper half zero-padded. Writes Re to output.
__global__ void __launch_bounds__(256, 6) k_inv_z(float* __restrict__ out){
    __shared__ float2 s[16*261];
    int x0 = blockIdx.x << 4, y = blockIdx.y, bb = blockIdx.z;
    int tid = threadIdx.x, xp = tid & 7, u = tid >> 3;
    const float2* base = g_B + ((size_t)bb << 24) + ((size_t)y << 8) + x0;
    const float4* base4 = (const float4*)base;
    float2* sl0 = s + (2*xp)*261;
    float2* sl1 = sl0 + 261;
#pragma unroll
    for (int c = 0; c < 2; ++c){
        int q = (c << 5) + u;
        int n0 = dr3(q);
        float4 v0 = make_float4(0.f,0.f,0.f,0.f);
        if (n0 >= 1) v0 = base4[(size_t)n0*32768 + xp];
        float4 v1 = base4[(size_t)(n0 + 64)*32768 + xp];
        float2 z2 = make_float2(0.f, 0.f);
        stage0_reg<1>(make_float2(v0.x,v0.y), make_float2(v1.x,v1.y), z2, z2, sl0, q);
        stage0_reg<1>(make_float2(v0.z,v0.w), make_float2(v1.z,v1.w), z2, z2, sl1, q);
    }
    fft_mid_x2<1,3>(sl0, sl1, u);
    float* ob = out + ((size_t)bb << 21) + (size_t)y*128 + (size_t)(x0 + 2*xp);
#pragma unroll
    for (int k = 0; k < 2; ++k){
        int j = (k << 5) + u;               // < 64
        float2 a0,a1,a2,a3, c0,c1,c2,c3;
        fft256_last<1>(sl0, j, a0,a1,a2,a3);
        fft256_last<1>(sl1, j, c0,c1,c2,c3);
        const float sc = 1.f/256.f;
        *(float2*)(ob + (size_t)j*16384)        = make_float2(a0.x*sc, c0.x*sc);
        *(float2*)(ob + (size_t)(j + 64)*16384) = make_float2(a1.x*sc, c1.x*sc);
    }
}

extern "C" void kernel_launch(void* const* d_in, const int* in_sizes, int n_in,
                              void* d_out, int out_size){
    (void)in_sizes; (void)n_in; (void)out_size;
    const float* in = (const float*)d_in[0];
    float* out = (float*)d_out;

    k_fwd_x        <<<dim3(32, 128, 2), 256>>>(in);
    k_fwd_y        <<<dim3(9,  128, 2), 256>>>();
    k_fwd_z        <<<dim3(9,  257, 2), 256>>>();
    k_resample_invx<<<dim3(16, 127, 2), 256>>>();
    k_inv_y        <<<dim3(8,  127, 2), 256>>>();
    k_inv_z        <<<dim3(8,  128, 2), 256>>>(out);
}